// round 4
// baseline (speedup 1.0000x reference)
#include <cuda_runtime.h>
#include <math.h>

#define BB 32
#define TT 512
#define HH 512
#define G4 2048

typedef unsigned long long u64;

// ---- packed f32x2 helpers (sm_103a dual-rate FP32 path; ptxas won't emit from C++) ----
__device__ __forceinline__ void fma2(u64& d, u64 a, u64 b) {
    asm("fma.rn.f32x2 %0, %1, %2, %0;" : "+l"(d) : "l"(a), "l"(b));
}
__device__ __forceinline__ u64 dup2(float v) {
    u64 r; asm("mov.b64 %0, {%1, %1};" : "=l"(r) : "f"(v)); return r;
}
__device__ __forceinline__ u64 pack_lo(float v) {
    u64 r; asm("mov.b64 %0, {%1, %2};" : "=l"(r) : "f"(v), "f"(0.0f)); return r;
}
__device__ __forceinline__ void unpack2(u64 v, float& lo, float& hi) {
    asm("mov.b64 {%0, %1}, %2;" : "=f"(lo), "=f"(hi) : "l"(v));
}
__device__ __forceinline__ float hsum2(u64 v) {
    float lo, hi; unpack2(v, lo, hi); return lo + hi;
}

// ---------------- device scratch (static; no dynamic allocation) ----------------
__device__ float    g_xg[(size_t)2 * TT * BB * G4];     // [dir][t][b][4H]  268 MB
__device__ float    g_hbuf[2 * 2 * BB * HH];            // [dir][ping][b][h]
__device__ unsigned g_bar[2 * TT];                      // per-dir per-step arrival counters

// ---------------- kernel 1: input projection GEMM (FFMA2 inner product) ----------------
// out[m][n] = sum_k x[m][k] * W[n][k] + b_ih[n] + b_hh[n]
// M = 16384 (m = b*512 + t), N = 4096 (dir*2048 + g), K = 512
__global__ __launch_bounds__(256)
void gemm_xg_kernel(const float* __restrict__ x,
                    const float* __restrict__ Wf, const float* __restrict__ Wb,
                    const float* __restrict__ bif, const float* __restrict__ bhf,
                    const float* __restrict__ bib, const float* __restrict__ bhb)
{
    __shared__ float As[8][132];
    __shared__ float Bs[8][132];
    const int tid   = threadIdx.x;
    const int ntile = blockIdx.x << 7;
    const int mtile = blockIdx.y << 7;
    const int dir   = ntile >> 11;
    const int nloc  = ntile & 2047;
    const float* __restrict__ W = dir ? Wb : Wf;

    const int lrow = tid >> 1;
    const int lk   = (tid & 1) << 2;

    const float* aG = x + (size_t)(mtile + lrow) * 512 + lk;
    const float* bG = W + (size_t)(nloc  + lrow) * 512 + lk;

    // acc2[p][j]: packed pair of m-rows (2p, 2p+1 in the old i-indexing) x n-col j
    u64 acc2[4][8];
#pragma unroll
    for (int p = 0; p < 4; ++p)
#pragma unroll
        for (int j = 0; j < 8; ++j) acc2[p][j] = 0ull;

    const int tm = tid & 15;
    const int tn = tid >> 4;

    float4 av = *(const float4*)aG;
    float4 bv = *(const float4*)bG;

    for (int kt = 0; kt < 64; ++kt) {
        As[lk+0][lrow] = av.x; As[lk+1][lrow] = av.y;
        As[lk+2][lrow] = av.z; As[lk+3][lrow] = av.w;
        Bs[lk+0][lrow] = bv.x; Bs[lk+1][lrow] = bv.y;
        Bs[lk+2][lrow] = bv.z; Bs[lk+3][lrow] = bv.w;
        __syncthreads();
        if (kt < 63) {
            av = *(const float4*)(aG + (kt + 1) * 8);
            bv = *(const float4*)(bG + (kt + 1) * 8);
        }
#pragma unroll
        for (int kk = 0; kk < 8; ++kk) {
            ulonglong2 A0 = *(const ulonglong2*)&As[kk][tm * 4];       // rows (tm*4+0,1),(+2,3)
            ulonglong2 A1 = *(const ulonglong2*)&As[kk][tm * 4 + 64];  // rows (64+tm*4+0,1),(+2,3)
            float4 b0 = *(const float4*)&Bs[kk][tn * 4];
            float4 b1 = *(const float4*)&Bs[kk][tn * 4 + 64];
            float bn[8] = {b0.x, b0.y, b0.z, b0.w, b1.x, b1.y, b1.z, b1.w};
#pragma unroll
            for (int j = 0; j < 8; ++j) {
                u64 bd = dup2(bn[j]);
                fma2(acc2[0][j], A0.x, bd);
                fma2(acc2[1][j], A0.y, bd);
                fma2(acc2[2][j], A1.x, bd);
                fma2(acc2[3][j], A1.y, bd);
            }
        }
        __syncthreads();
    }

    // unpack: pair p -> (i=2p, i=2p+1) in the old mi mapping
    float acc[8][8];
#pragma unroll
    for (int p = 0; p < 4; ++p)
#pragma unroll
        for (int j = 0; j < 8; ++j)
            unpack2(acc2[p][j], acc[2 * p][j], acc[2 * p + 1][j]);

    const float* bi = dir ? bib : bif;
    const float* bh = dir ? bhb : bhf;
    const int g0 = nloc + tn * 4;
    const int g1 = g0 + 64;
    float bs0[4], bs1[4];
#pragma unroll
    for (int j = 0; j < 4; ++j) { bs0[j] = bi[g0+j] + bh[g0+j]; bs1[j] = bi[g1+j] + bh[g1+j]; }

#pragma unroll
    for (int i = 0; i < 8; ++i) {
        int mi = (i < 4) ? (tm * 4 + i) : (64 + tm * 4 + (i - 4));
        int m  = mtile + mi;
        int b  = m >> 9;
        int t  = m & 511;
        float* orow = g_xg + (((size_t)dir * TT + t) * BB + b) * G4;
        float4 o0, o1;
        o0.x = acc[i][0] + bs0[0]; o0.y = acc[i][1] + bs0[1];
        o0.z = acc[i][2] + bs0[2]; o0.w = acc[i][3] + bs0[3];
        o1.x = acc[i][4] + bs1[0]; o1.y = acc[i][5] + bs1[1];
        o1.z = acc[i][6] + bs1[2]; o1.w = acc[i][7] + bs1[3];
        *(float4*)&orow[g0] = o0;
        *(float4*)&orow[g1] = o1;
    }
}

// ---------------- kernel 2: persistent recurrent scan (FFMA2 over k-pairs) ----------------
// 128 CTAs (64/dir), 256 threads, 1 CTA/SM. CTA owns 8 h-columns for all 32 batches.
// W_hh rows in SMEM for the whole scan; h staged per step via __ldcg.
#define SCAN_SMEM_FLOATS (32*516 + 32*516 + 256*4 + 256 + 32)
#define SCAN_SMEM_BYTES  (SCAN_SMEM_FLOATS * 4)

__global__ __launch_bounds__(256, 1)
void lstm_scan_kernel(const int* __restrict__ lengths,
                      const float* __restrict__ Whhf,
                      const float* __restrict__ Whhb,
                      float* __restrict__ out)
{
    extern __shared__ float sm[];
    float* sh_h = sm;                           // [32][516] padded h_prev
    float* sh_w = sm + 32 * 516;                // [32][516]: row r=(gate*8+jj)
    float* sh_g = sh_w + 32 * 516;              // [256][4] gates per cell
    float* sh_c = sh_g + 256 * 4;               // [256] cell state
    int*   sh_len = (int*)(sh_c + 256);         // [32]

    const int tid   = threadIdx.x;
    const int d     = blockIdx.x >> 6;
    const int cta   = blockIdx.x & 63;
    const int jbase = cta << 3;
    const float* __restrict__ Wd = d ? Whhb : Whhf;

    if (tid < 32) sh_len[tid] = lengths[tid];
    sh_c[tid] = 0.f;

    // preload W_hh rows (gate 0..3, col jbase..jbase+7) -> sh_w[gate*8+jj][k]
    for (int i = tid; i < (32 * 512) / 4; i += 256) {
        int flat = i << 2;
        int r = flat >> 9;
        int k = flat & 511;
        int gate = r >> 3, jj = r & 7;
        float4 v = *(const float4*)(Wd + ((size_t)(gate * 512 + jbase + jj)) * 512 + k);
        *(float4*)&sh_w[r * 516 + k] = v;
    }

    const int jj  = tid & 7;
    const int gp  = (tid >> 3) & 1;
    const int b0  = (tid >> 4) << 1;
    const int col = jbase + jj;
    const float* wrow0 = &sh_w[((gp * 2 + 0) * 8 + jj) * 516];
    const float* wrow1 = &sh_w[((gp * 2 + 1) * 8 + jj) * 516];

    unsigned* bar = g_bar  + d * TT;
    float*    hb  = g_hbuf + (size_t)d * 2 * BB * HH;

    const int cb = tid >> 3;
    const int cj = tid & 7;
    const int hc = jbase + cj;

    __syncthreads();

    for (int s = 0; s < TT; ++s) {
        const int tt = d ? (511 - s) : s;
        const int p  = s & 1;

        // xg loads first (overlap L2 latency with staging)
        const float* xgb = g_xg + (((size_t)d * TT + tt) * BB) * G4;
        u64 A00 = pack_lo(__ldg(xgb + (size_t)(b0 + 0) * G4 + (gp * 2 + 0) * 512 + col));
        u64 A01 = pack_lo(__ldg(xgb + (size_t)(b0 + 0) * G4 + (gp * 2 + 1) * 512 + col));
        u64 A10 = pack_lo(__ldg(xgb + (size_t)(b0 + 1) * G4 + (gp * 2 + 0) * 512 + col));
        u64 A11 = pack_lo(__ldg(xgb + (size_t)(b0 + 1) * G4 + (gp * 2 + 1) * 512 + col));

        // stage h_prev (L2-coherent loads; L1 may be stale across SMs)
        const float* hsrc = hb + p * BB * HH;
        for (int i = tid; i < (BB * HH) / 4; i += 256) {
            int fl = i << 2;
            int b  = fl >> 9, k = fl & 511;
            float4 v = __ldcg((const float4*)(hsrc + fl));
            *(float4*)&sh_h[b * 516 + k] = v;
        }
        __syncthreads();

        // gates += h @ W_hh^T, packed pairs over k (all operands in smem)
#pragma unroll 4
        for (int kq = 0; kq < 128; ++kq) {
            ulonglong2 wa = *(const ulonglong2*)(wrow0 + kq * 4);
            ulonglong2 wb = *(const ulonglong2*)(wrow1 + kq * 4);
            ulonglong2 h0 = *(const ulonglong2*)&sh_h[(b0 + 0) * 516 + kq * 4];
            ulonglong2 h1 = *(const ulonglong2*)&sh_h[(b0 + 1) * 516 + kq * 4];
            fma2(A00, h0.x, wa.x); fma2(A00, h0.y, wa.y);
            fma2(A01, h0.x, wb.x); fma2(A01, h0.y, wb.y);
            fma2(A10, h1.x, wa.x); fma2(A10, h1.y, wa.y);
            fma2(A11, h1.x, wb.x); fma2(A11, h1.y, wb.y);
        }
        sh_g[((b0 + 0) * 8 + jj) * 4 + gp * 2 + 0] = hsum2(A00);
        sh_g[((b0 + 0) * 8 + jj) * 4 + gp * 2 + 1] = hsum2(A01);
        sh_g[((b0 + 1) * 8 + jj) * 4 + gp * 2 + 0] = hsum2(A10);
        sh_g[((b0 + 1) * 8 + jj) * 4 + gp * 2 + 1] = hsum2(A11);
        __syncthreads();

        // cell update: one (b, j) cell per thread
        float* hnext = hb + (p ^ 1) * BB * HH;
        {
            float4 gv = *(float4*)&sh_g[tid * 4];
            float ig = 1.f / (1.f + expf(-gv.x));
            float fg = 1.f / (1.f + expf(-gv.y));
            float gg = tanhf(gv.z);
            float og = 1.f / (1.f + expf(-gv.w));
            float c  = sh_c[tid];
            float cn = fg * c + ig * gg;
            float hn = og * tanhf(cn);
            float h;
            if (tt < sh_len[cb]) { c = cn; h = hn; }
            else                 { h = sh_h[cb * 516 + hc]; }
            sh_c[tid] = c;
            __stcg(hnext + cb * HH + hc, h);
            out[((size_t)(cb * TT + tt)) * 1024 + d * HH + hc] = h;
        }

        // cross-CTA barrier (per direction, 64 arrivals); single-thread fences
        __syncthreads();
        if (s < TT - 1 && tid == 0) {
            __threadfence();
            atomicAdd(&bar[s], 1u);
            while (*((volatile unsigned*)&bar[s]) < 64u) { __nanosleep(32); }
            __threadfence();
        }
        __syncthreads();
    }
}

extern "C" void kernel_launch(void* const* d_in, const int* in_sizes, int n_in,
                              void* d_out, int out_size)
{
    const float* x    = (const float*)d_in[0];
    const int*   len  = (const int*)  d_in[1];
    const float* Wihf = (const float*)d_in[2];
    const float* Whhf = (const float*)d_in[3];
    const float* bihf = (const float*)d_in[4];
    const float* bhhf = (const float*)d_in[5];
    const float* Wihb = (const float*)d_in[6];
    const float* Whhb = (const float*)d_in[7];
    const float* bihb = (const float*)d_in[8];
    const float* bhhb = (const float*)d_in[9];
    float* out = (float*)d_out;

    void* barp = 0; void* hbp = 0;
    cudaGetSymbolAddress(&barp, g_bar);
    cudaGetSymbolAddress(&hbp,  g_hbuf);
    cudaMemsetAsync(barp, 0, 2 * TT * sizeof(unsigned));
    cudaMemsetAsync(hbp,  0, (size_t)2 * 2 * BB * HH * sizeof(float));

    dim3 ggrid(32, 128);
    gemm_xg_kernel<<<ggrid, 256>>>(x, Wihf, Wihb, bihf, bhhf, bihb, bhhb);

    cudaFuncSetAttribute(lstm_scan_kernel,
                         cudaFuncAttributeMaxDynamicSharedMemorySize, SCAN_SMEM_BYTES);
    lstm_scan_kernel<<<128, 256, SCAN_SMEM_BYTES>>>(len, Whhf, Whhb, out);
}

// round 8
// speedup vs baseline: 1.6518x; 1.6518x over previous
#include <cuda_runtime.h>
#include <math.h>

#define BB 32
#define TT 512
#define HH 512
#define G4 2048

// ---------------- device scratch (static; no dynamic allocation) ----------------
__device__ float    g_xg[(size_t)2 * TT * BB * G4];     // [dir][t][b][4H]  268 MB
__device__ float    g_hbuf[2 * 2 * BB * HH];            // [dir][ping][b][h]
__device__ unsigned g_bar[2 * TT];                      // per-dir per-step arrival counters

// ---- fast transcendentals (clamped; rel err ~1e-6, threshold is 1e-3) ----
__device__ __forceinline__ float fsig(float x) {
    x = fminf(30.f, fmaxf(-30.f, x));
    return __fdividef(1.f, 1.f + __expf(-x));
}
__device__ __forceinline__ float ftanh(float x) {
    x = fminf(15.f, fmaxf(-15.f, x));
    float e = __expf(2.f * x);
    return __fdividef(e - 1.f, e + 1.f);
}

// ---------------- kernel 1: input projection GEMM (double-buffered smem) ----------------
// out[m][n] = sum_k x[m][k] * W[n][k] + b_ih[n] + b_hh[n]
// M = 16384 (m = b*512 + t), N = 4096 (dir*2048 + g), K = 512
__global__ __launch_bounds__(256)
void gemm_xg_kernel(const float* __restrict__ x,
                    const float* __restrict__ Wf, const float* __restrict__ Wb,
                    const float* __restrict__ bif, const float* __restrict__ bhf,
                    const float* __restrict__ bib, const float* __restrict__ bhb)
{
    __shared__ float As[2][8][132];
    __shared__ float Bs[2][8][132];
    const int tid   = threadIdx.x;
    const int ntile = blockIdx.x << 7;
    const int mtile = blockIdx.y << 7;
    const int dir   = ntile >> 11;
    const int nloc  = ntile & 2047;
    const float* __restrict__ W = dir ? Wb : Wf;

    const int lrow = tid >> 1;
    const int lk   = (tid & 1) << 2;

    const float* aG = x + (size_t)(mtile + lrow) * 512 + lk;
    const float* bG = W + (size_t)(nloc  + lrow) * 512 + lk;

    float acc[8][8];
#pragma unroll
    for (int i = 0; i < 8; ++i)
#pragma unroll
        for (int j = 0; j < 8; ++j) acc[i][j] = 0.f;

    const int tm = tid & 15;
    const int tn = tid >> 4;

    // prologue: fill buffer 0
    {
        float4 av = *(const float4*)aG;
        float4 bv = *(const float4*)bG;
        As[0][lk+0][lrow] = av.x; As[0][lk+1][lrow] = av.y;
        As[0][lk+2][lrow] = av.z; As[0][lk+3][lrow] = av.w;
        Bs[0][lk+0][lrow] = bv.x; Bs[0][lk+1][lrow] = bv.y;
        Bs[0][lk+2][lrow] = bv.z; Bs[0][lk+3][lrow] = bv.w;
    }
    __syncthreads();

    int p = 0;
    for (int kt = 0; kt < 64; ++kt) {
        float4 av, bv;
        if (kt < 63) {
            av = *(const float4*)(aG + (kt + 1) * 8);
            bv = *(const float4*)(bG + (kt + 1) * 8);
        }
#pragma unroll
        for (int kk = 0; kk < 8; ++kk) {
            float4 a0 = *(const float4*)&As[p][kk][tm * 4];
            float4 a1 = *(const float4*)&As[p][kk][tm * 4 + 64];
            float4 b0 = *(const float4*)&Bs[p][kk][tn * 4];
            float4 b1 = *(const float4*)&Bs[p][kk][tn * 4 + 64];
            float am[8] = {a0.x, a0.y, a0.z, a0.w, a1.x, a1.y, a1.z, a1.w};
            float bn[8] = {b0.x, b0.y, b0.z, b0.w, b1.x, b1.y, b1.z, b1.w};
#pragma unroll
            for (int i = 0; i < 8; ++i)
#pragma unroll
                for (int j = 0; j < 8; ++j)
                    acc[i][j] = fmaf(am[i], bn[j], acc[i][j]);
        }
        if (kt < 63) {
            int q = p ^ 1;
            As[q][lk+0][lrow] = av.x; As[q][lk+1][lrow] = av.y;
            As[q][lk+2][lrow] = av.z; As[q][lk+3][lrow] = av.w;
            Bs[q][lk+0][lrow] = bv.x; Bs[q][lk+1][lrow] = bv.y;
            Bs[q][lk+2][lrow] = bv.z; Bs[q][lk+3][lrow] = bv.w;
            __syncthreads();
            p = q;
        }
    }

    const float* bi = dir ? bib : bif;
    const float* bh = dir ? bhb : bhf;
    const int g0 = nloc + tn * 4;
    const int g1 = g0 + 64;
    float bs0[4], bs1[4];
#pragma unroll
    for (int j = 0; j < 4; ++j) { bs0[j] = bi[g0+j] + bh[g0+j]; bs1[j] = bi[g1+j] + bh[g1+j]; }

#pragma unroll
    for (int i = 0; i < 8; ++i) {
        int mi = (i < 4) ? (tm * 4 + i) : (64 + tm * 4 + (i - 4));
        int m  = mtile + mi;
        int b  = m >> 9;
        int t  = m & 511;
        float* orow = g_xg + (((size_t)dir * TT + t) * BB + b) * G4;
        float4 o0, o1;
        o0.x = acc[i][0] + bs0[0]; o0.y = acc[i][1] + bs0[1];
        o0.z = acc[i][2] + bs0[2]; o0.w = acc[i][3] + bs0[3];
        o1.x = acc[i][4] + bs1[0]; o1.y = acc[i][5] + bs1[1];
        o1.z = acc[i][6] + bs1[2]; o1.w = acc[i][7] + bs1[3];
        *(float4*)&orow[g0] = o0;
        *(float4*)&orow[g1] = o1;
    }
}

// ---------------- kernel 2: persistent recurrent scan ----------------
// 128 CTAs (64/dir), 256 threads, 1 CTA/SM. CTA owns 8 h-columns for all 32 batches.
// W_hh rows live in SMEM for the whole scan. h staged per step via __ldcg.
// Release/acquire barrier (no gpu-scope fences); xg prefetched across the barrier.
#define SCAN_SMEM_FLOATS (32*516 + 32*516 + 256*4 + 256 + 32)
#define SCAN_SMEM_BYTES  (SCAN_SMEM_FLOATS * 4)

__global__ __launch_bounds__(256, 1)
void lstm_scan_kernel(const int* __restrict__ lengths,
                      const float* __restrict__ Whhf,
                      const float* __restrict__ Whhb,
                      float* __restrict__ out)
{
    extern __shared__ float sm[];
    float* sh_h = sm;                           // [32][516] padded h_prev
    float* sh_w = sm + 32 * 516;                // [32][516]: row r=(gate*8+jj)
    float* sh_g = sh_w + 32 * 516;              // [256][4] gates per cell
    float* sh_c = sh_g + 256 * 4;               // [256] cell state
    int*   sh_len = (int*)(sh_c + 256);         // [32]

    const int tid   = threadIdx.x;
    const int d     = blockIdx.x >> 6;
    const int cta   = blockIdx.x & 63;
    const int jbase = cta << 3;
    const float* __restrict__ Wd = d ? Whhb : Whhf;

    if (tid < 32) sh_len[tid] = lengths[tid];
    sh_c[tid] = 0.f;

    // preload W_hh rows (gate 0..3, col jbase..jbase+7) -> sh_w[gate*8+jj][k]
    for (int i = tid; i < (32 * 512) / 4; i += 256) {
        int flat = i << 2;
        int r = flat >> 9;
        int k = flat & 511;
        int gate = r >> 3, jj = r & 7;
        float4 v = *(const float4*)(Wd + ((size_t)(gate * 512 + jbase + jj)) * 512 + k);
        *(float4*)&sh_w[r * 516 + k] = v;
    }

    const int jj  = tid & 7;
    const int gp  = (tid >> 3) & 1;
    const int b0  = (tid >> 4) << 1;
    const int col = jbase + jj;
    const float* wrow0 = &sh_w[((gp * 2 + 0) * 8 + jj) * 516];
    const float* wrow1 = &sh_w[((gp * 2 + 1) * 8 + jj) * 516];

    unsigned* bar = g_bar  + d * TT;
    float*    hb  = g_hbuf + (size_t)d * 2 * BB * HH;

    const int cb = tid >> 3;
    const int cj = tid & 7;
    const int hc = jbase + cj;

    // per-thread xg offsets (constant across steps except t)
    const size_t xo00 = (size_t)(b0 + 0) * G4 + (gp * 2 + 0) * 512 + col;
    const size_t xo01 = (size_t)(b0 + 0) * G4 + (gp * 2 + 1) * 512 + col;
    const size_t xo10 = (size_t)(b0 + 1) * G4 + (gp * 2 + 0) * 512 + col;
    const size_t xo11 = (size_t)(b0 + 1) * G4 + (gp * 2 + 1) * 512 + col;

    __syncthreads();

    // prologue: xg for step 0
    const int t0 = d ? 511 : 0;
    const float* xg0 = g_xg + (((size_t)d * TT + t0) * BB) * G4;
    float x00 = __ldg(xg0 + xo00);
    float x01 = __ldg(xg0 + xo01);
    float x10 = __ldg(xg0 + xo10);
    float x11 = __ldg(xg0 + xo11);

    for (int s = 0; s < TT; ++s) {
        const int tt = d ? (511 - s) : s;
        const int p  = s & 1;

        // stage h_prev (L2-coherent loads; L1 may be stale across SMs)
        const float* hsrc = hb + p * BB * HH;
        for (int i = tid; i < (BB * HH) / 4; i += 256) {
            int fl = i << 2;
            int b  = fl >> 9, k = fl & 511;
            float4 v = __ldcg((const float4*)(hsrc + fl));
            *(float4*)&sh_h[b * 516 + k] = v;
        }
        __syncthreads();

        // gates = xg + h @ W_hh^T   (all operands in smem)
        float a00 = x00, a01 = x01, a10 = x10, a11 = x11;
#pragma unroll 4
        for (int kq = 0; kq < 128; ++kq) {
            float4 wa = *(const float4*)(wrow0 + kq * 4);
            float4 wb = *(const float4*)(wrow1 + kq * 4);
            float4 h0 = *(const float4*)&sh_h[(b0 + 0) * 516 + kq * 4];
            float4 h1 = *(const float4*)&sh_h[(b0 + 1) * 516 + kq * 4];
            a00 = fmaf(h0.x, wa.x, a00); a00 = fmaf(h0.y, wa.y, a00);
            a00 = fmaf(h0.z, wa.z, a00); a00 = fmaf(h0.w, wa.w, a00);
            a01 = fmaf(h0.x, wb.x, a01); a01 = fmaf(h0.y, wb.y, a01);
            a01 = fmaf(h0.z, wb.z, a01); a01 = fmaf(h0.w, wb.w, a01);
            a10 = fmaf(h1.x, wa.x, a10); a10 = fmaf(h1.y, wa.y, a10);
            a10 = fmaf(h1.z, wa.z, a10); a10 = fmaf(h1.w, wa.w, a10);
            a11 = fmaf(h1.x, wb.x, a11); a11 = fmaf(h1.y, wb.y, a11);
            a11 = fmaf(h1.z, wb.z, a11); a11 = fmaf(h1.w, wb.w, a11);
        }
        sh_g[((b0 + 0) * 8 + jj) * 4 + gp * 2 + 0] = a00;
        sh_g[((b0 + 0) * 8 + jj) * 4 + gp * 2 + 1] = a01;
        sh_g[((b0 + 1) * 8 + jj) * 4 + gp * 2 + 0] = a10;
        sh_g[((b0 + 1) * 8 + jj) * 4 + gp * 2 + 1] = a11;
        __syncthreads();

        // cell update: one (b, j) cell per thread; only hnext store is on the
        // inter-CTA critical path — out[] store deferred past the barrier arrive.
        float* hnext = hb + (p ^ 1) * BB * HH;
        float hval;
        {
            float4 gv = *(float4*)&sh_g[tid * 4];
            float ig = fsig(gv.x);
            float fg = fsig(gv.y);
            float gg = ftanh(gv.z);
            float og = fsig(gv.w);
            float c  = sh_c[tid];
            float cn = fg * c + ig * gg;
            float hn = og * ftanh(cn);
            if (tt < sh_len[cb]) { c = cn; hval = hn; }
            else                 { hval = sh_h[cb * 516 + hc]; }
            sh_c[tid] = c;
            __stcg(hnext + cb * HH + hc, hval);
        }
        __syncthreads();   // all hnext stores done CTA-wide

        if (s < TT - 1) {
            // release: publish our h stores, then overlap prefetch+out with the wait
            if (tid == 0) {
                asm volatile("red.release.gpu.global.add.u32 [%0], 1;"
                             :: "l"(&bar[s]) : "memory");
            }
            // prefetch next step's xg (DRAM latency hidden behind the barrier)
            const int tn2 = d ? (510 - s) : (s + 1);
            const float* xgn = g_xg + (((size_t)d * TT + tn2) * BB) * G4;
            x00 = __ldg(xgn + xo00);
            x01 = __ldg(xgn + xo01);
            x10 = __ldg(xgn + xo10);
            x11 = __ldg(xgn + xo11);
            // output store (not on the h critical path)
            out[((size_t)(cb * TT + tt)) * 1024 + d * HH + hc] = hval;

            if (tid == 0) {
                unsigned v;
                for (;;) {
                    asm volatile("ld.acquire.gpu.global.u32 %0, [%1];"
                                 : "=r"(v) : "l"(&bar[s]) : "memory");
                    if (v >= 64u) break;
                    __nanosleep(32);
                }
            }
            __syncthreads();
        } else {
            out[((size_t)(cb * TT + tt)) * 1024 + d * HH + hc] = hval;
        }
    }
}

extern "C" void kernel_launch(void* const* d_in, const int* in_sizes, int n_in,
                              void* d_out, int out_size)
{
    const float* x    = (const float*)d_in[0];
    const int*   len  = (const int*)  d_in[1];
    const float* Wihf = (const float*)d_in[2];
    const float* Whhf = (const float*)d_in[3];
    const float* bihf = (const float*)d_in[4];
    const float* bhhf = (const float*)d_in[5];
    const float* Wihb = (const float*)d_in[6];
    const float* Whhb = (const float*)d_in[7];
    const float* bihb = (const float*)d_in[8];
    const float* bhhb = (const float*)d_in[9];
    float* out = (float*)d_out;

    void* barp = 0; void* hbp = 0;
    cudaGetSymbolAddress(&barp, g_bar);
    cudaGetSymbolAddress(&hbp,  g_hbuf);
    cudaMemsetAsync(barp, 0, 2 * TT * sizeof(unsigned));
    cudaMemsetAsync(hbp,  0, (size_t)2 * 2 * BB * HH * sizeof(float));

    dim3 ggrid(32, 128);
    gemm_xg_kernel<<<ggrid, 256>>>(x, Wihf, Wihb, bihf, bhhf, bihb, bhhb);

    cudaFuncSetAttribute(lstm_scan_kernel,
                         cudaFuncAttributeMaxDynamicSharedMemorySize, SCAN_SMEM_BYTES);
    lstm_scan_kernel<<<128, 256, SCAN_SMEM_BYTES>>>(len, Whhf, Whhb, out);
}

// round 9
// speedup vs baseline: 2.1423x; 1.2970x over previous
#include <cuda_runtime.h>
#include <math.h>

#define BB 32
#define TT 512
#define HH 512
#define G4 2048

// ---------------- device scratch (static; no dynamic allocation) ----------------
__device__ float    g_xg[(size_t)2 * TT * BB * G4];     // [dir][t][b][4H] (b = ACTUAL batch)
__device__ float    g_hbuf[2 * 2 * BB * HH];            // [dir][ping][rank][h] (RANK-indexed)
__device__ unsigned g_bar[2 * TT];                      // per-dir per-step arrival counters

// ---- fast transcendentals (clamped; rel err ~1e-6, threshold is 1e-3) ----
__device__ __forceinline__ float fsig(float x) {
    x = fminf(30.f, fmaxf(-30.f, x));
    return __fdividef(1.f, 1.f + __expf(-x));
}
__device__ __forceinline__ float ftanh(float x) {
    x = fminf(15.f, fmaxf(-15.f, x));
    float e = __expf(2.f * x);
    return __fdividef(e - 1.f, e + 1.f);
}

// ---------------- kernel 1: input projection GEMM (double-buffered, dead-tile skip) ----
// out[m][n] = sum_k x[m][k] * W[n][k] + b_ih[n] + b_hh[n]
// M = 16384 (m = b*512 + t), N = 4096 (dir*2048 + g), K = 512.
// A 128-row m-tile spans t in [mtile&511, +128) of ONE batch; if t_start >= len[b]
// the whole tile's xg is never read by the scan -> early exit.
__global__ __launch_bounds__(256)
void gemm_xg_kernel(const float* __restrict__ x,
                    const float* __restrict__ Wf, const float* __restrict__ Wb,
                    const float* __restrict__ bif, const float* __restrict__ bhf,
                    const float* __restrict__ bib, const float* __restrict__ bhb,
                    const int* __restrict__ lengths)
{
    const int ntile = blockIdx.x << 7;
    const int mtile = blockIdx.y << 7;
    {
        const int bb = mtile >> 9;
        const int tstart = mtile & 511;
        if (tstart >= __ldg(&lengths[bb])) return;   // xg of dead steps is never read
    }

    __shared__ float As[2][8][132];
    __shared__ float Bs[2][8][132];
    const int tid   = threadIdx.x;
    const int dir   = ntile >> 11;
    const int nloc  = ntile & 2047;
    const float* __restrict__ W = dir ? Wb : Wf;

    const int lrow = tid >> 1;
    const int lk   = (tid & 1) << 2;

    const float* aG = x + (size_t)(mtile + lrow) * 512 + lk;
    const float* bG = W + (size_t)(nloc  + lrow) * 512 + lk;

    float acc[8][8];
#pragma unroll
    for (int i = 0; i < 8; ++i)
#pragma unroll
        for (int j = 0; j < 8; ++j) acc[i][j] = 0.f;

    const int tm = tid & 15;
    const int tn = tid >> 4;

    {
        float4 av = *(const float4*)aG;
        float4 bv = *(const float4*)bG;
        As[0][lk+0][lrow] = av.x; As[0][lk+1][lrow] = av.y;
        As[0][lk+2][lrow] = av.z; As[0][lk+3][lrow] = av.w;
        Bs[0][lk+0][lrow] = bv.x; Bs[0][lk+1][lrow] = bv.y;
        Bs[0][lk+2][lrow] = bv.z; Bs[0][lk+3][lrow] = bv.w;
    }
    __syncthreads();

    int p = 0;
    for (int kt = 0; kt < 64; ++kt) {
        float4 av, bv;
        if (kt < 63) {
            av = *(const float4*)(aG + (kt + 1) * 8);
            bv = *(const float4*)(bG + (kt + 1) * 8);
        }
#pragma unroll
        for (int kk = 0; kk < 8; ++kk) {
            float4 a0 = *(const float4*)&As[p][kk][tm * 4];
            float4 a1 = *(const float4*)&As[p][kk][tm * 4 + 64];
            float4 b0 = *(const float4*)&Bs[p][kk][tn * 4];
            float4 b1 = *(const float4*)&Bs[p][kk][tn * 4 + 64];
            float am[8] = {a0.x, a0.y, a0.z, a0.w, a1.x, a1.y, a1.z, a1.w};
            float bn[8] = {b0.x, b0.y, b0.z, b0.w, b1.x, b1.y, b1.z, b1.w};
#pragma unroll
            for (int i = 0; i < 8; ++i)
#pragma unroll
                for (int j = 0; j < 8; ++j)
                    acc[i][j] = fmaf(am[i], bn[j], acc[i][j]);
        }
        if (kt < 63) {
            int q = p ^ 1;
            As[q][lk+0][lrow] = av.x; As[q][lk+1][lrow] = av.y;
            As[q][lk+2][lrow] = av.z; As[q][lk+3][lrow] = av.w;
            Bs[q][lk+0][lrow] = bv.x; Bs[q][lk+1][lrow] = bv.y;
            Bs[q][lk+2][lrow] = bv.z; Bs[q][lk+3][lrow] = bv.w;
            __syncthreads();
            p = q;
        }
    }

    const float* bi = dir ? bib : bif;
    const float* bh = dir ? bhb : bhf;
    const int g0 = nloc + tn * 4;
    const int g1 = g0 + 64;
    float bs0[4], bs1[4];
#pragma unroll
    for (int j = 0; j < 4; ++j) { bs0[j] = bi[g0+j] + bh[g0+j]; bs1[j] = bi[g1+j] + bh[g1+j]; }

#pragma unroll
    for (int i = 0; i < 8; ++i) {
        int mi = (i < 4) ? (tm * 4 + i) : (64 + tm * 4 + (i - 4));
        int m  = mtile + mi;
        int b  = m >> 9;
        int t  = m & 511;
        float* orow = g_xg + (((size_t)dir * TT + t) * BB + b) * G4;
        float4 o0, o1;
        o0.x = acc[i][0] + bs0[0]; o0.y = acc[i][1] + bs0[1];
        o0.z = acc[i][2] + bs0[2]; o0.w = acc[i][3] + bs0[3];
        o1.x = acc[i][4] + bs1[0]; o1.y = acc[i][5] + bs1[1];
        o1.z = acc[i][6] + bs1[2]; o1.w = acc[i][7] + bs1[3];
        *(float4*)&orow[g0] = o0;
        *(float4*)&orow[g1] = o1;
    }
}

// ---------------- kernel 2: persistent recurrent scan (length-sorted rank space) -------
// 128 CTAs (64/dir), 256 threads, 1 CTA/SM. CTA owns 8 h-columns for all 32 batches.
// Batches sorted by length into RANKS; warp w owns ranks 4w..4w+3 (adjacent lengths)
// -> warp-uniform dead-skip of the gate GEMM. h/c for a cell live in registers; the
// hbuf/sh_h/sh_g state is rank-indexed. All CTAs share the same alive pattern.
#define SCAN_SMEM_FLOATS (32*516 + 32*516 + 256*4 + 64)
#define SCAN_SMEM_BYTES  (SCAN_SMEM_FLOATS * 4)

__global__ __launch_bounds__(256, 1)
void lstm_scan_kernel(const int* __restrict__ lengths,
                      const float* __restrict__ Whhf,
                      const float* __restrict__ Whhb,
                      float* __restrict__ out)
{
    extern __shared__ float sm[];
    float* sh_h = sm;                           // [32][516] padded h_prev (rank-indexed)
    float* sh_w = sm + 32 * 516;                // [32][516]: row r=(gate*8+jj)
    float* sh_g = sh_w + 32 * 516;              // [256][4] gates per cell (rank-indexed)
    int*   sh_perm = (int*)(sh_g + 256 * 4);    // [32] rank -> actual batch
    int*   sh_slen = sh_perm + 32;              // [32] rank -> length (ascending)

    const int tid   = threadIdx.x;
    const int d     = blockIdx.x >> 6;
    const int cta   = blockIdx.x & 63;
    const int jbase = cta << 3;
    const float* __restrict__ Wd = d ? Whhb : Whhf;

    // --- rank batches by length (ascending, stable) ---
    __shared__ int sh_tmp[32];
    if (tid < 32) sh_tmp[tid] = lengths[tid];
    __syncthreads();
    if (tid < 32) {
        int L = sh_tmp[tid];
        int r = 0;
#pragma unroll
        for (int j = 0; j < 32; ++j) {
            int Lj = sh_tmp[j];
            r += (Lj < L) || (Lj == L && j < tid);
        }
        sh_perm[r] = tid;
        sh_slen[r] = L;
    }

    // preload W_hh rows (gate 0..3, col jbase..jbase+7) -> sh_w[gate*8+jj][k]
    for (int i = tid; i < (32 * 512) / 4; i += 256) {
        int flat = i << 2;
        int r = flat >> 9;
        int k = flat & 511;
        int gate = r >> 3, jj = r & 7;
        float4 v = *(const float4*)(Wd + ((size_t)(gate * 512 + jbase + jj)) * 512 + k);
        *(float4*)&sh_w[r * 516 + k] = v;
    }
    __syncthreads();

    // gate-compute mapping (rank space): jj 0..7, gate-pair gp, rank pair r0
    const int jj  = tid & 7;
    const int gp  = (tid >> 3) & 1;
    const int r0  = (tid >> 4) << 1;            // ranks r0, r0+1; warp w owns ranks 4w..4w+3
    const int col = jbase + jj;
    const float* wrow0 = &sh_w[((gp * 2 + 0) * 8 + jj) * 516];
    const float* wrow1 = &sh_w[((gp * 2 + 1) * 8 + jj) * 516];
    const int wdl = sh_slen[((tid >> 5) << 2) + 3];    // warp deadline = max len of its 4 ranks
    const int ab0 = sh_perm[r0];
    const int ab1 = sh_perm[r0 + 1];
    const size_t xo00 = (size_t)ab0 * G4 + (gp * 2 + 0) * 512 + col;
    const size_t xo01 = (size_t)ab0 * G4 + (gp * 2 + 1) * 512 + col;
    const size_t xo10 = (size_t)ab1 * G4 + (gp * 2 + 0) * 512 + col;
    const size_t xo11 = (size_t)ab1 * G4 + (gp * 2 + 1) * 512 + col;

    // cell-update mapping (rank space): one cell per thread, h/c in registers
    const int cr    = tid >> 3;                 // rank 0..31
    const int hcol  = jbase + (tid & 7);
    const int myb   = sh_perm[cr];              // actual batch (for out[])
    const int mylen = sh_slen[cr];
    float hreg = 0.f, creg = 0.f;

    unsigned* bar = g_bar  + d * TT;
    float*    hb  = g_hbuf + (size_t)d * 2 * BB * HH;

    // prologue: xg for step 0 (garbage if dead -> unused)
    const int t0 = d ? 511 : 0;
    const float* xg0 = g_xg + (((size_t)d * TT + t0) * BB) * G4;
    float x00 = 0.f, x01 = 0.f, x10 = 0.f, x11 = 0.f;
    if (t0 < wdl) {
        x00 = __ldg(xg0 + xo00); x01 = __ldg(xg0 + xo01);
        x10 = __ldg(xg0 + xo10); x11 = __ldg(xg0 + xo11);
    }

    for (int s = 0; s < TT; ++s) {
        const int tt = d ? (511 - s) : s;
        const int p  = s & 1;

        // stage h_prev, alive ranks only (L2-coherent; hbuf is rank-indexed)
        const float* hsrc = hb + p * BB * HH;
        for (int i = tid; i < (BB * HH) / 4; i += 256) {
            int fl = i << 2;
            int r  = fl >> 9, k = fl & 511;
            if (tt < sh_slen[r]) {
                float4 v = __ldcg((const float4*)(hsrc + fl));
                *(float4*)&sh_h[r * 516 + k] = v;
            }
        }
        __syncthreads();

        // gates = xg + h @ W_hh^T -- skipped when the warp's 4 ranks are all dead
        if (tt < wdl) {
            float a00 = x00, a01 = x01, a10 = x10, a11 = x11;
#pragma unroll 4
            for (int kq = 0; kq < 128; ++kq) {
                float4 wa = *(const float4*)(wrow0 + kq * 4);
                float4 wb = *(const float4*)(wrow1 + kq * 4);
                float4 h0 = *(const float4*)&sh_h[(r0 + 0) * 516 + kq * 4];
                float4 h1 = *(const float4*)&sh_h[(r0 + 1) * 516 + kq * 4];
                a00 = fmaf(h0.x, wa.x, a00); a00 = fmaf(h0.y, wa.y, a00);
                a00 = fmaf(h0.z, wa.z, a00); a00 = fmaf(h0.w, wa.w, a00);
                a01 = fmaf(h0.x, wb.x, a01); a01 = fmaf(h0.y, wb.y, a01);
                a01 = fmaf(h0.z, wb.z, a01); a01 = fmaf(h0.w, wb.w, a01);
                a10 = fmaf(h1.x, wa.x, a10); a10 = fmaf(h1.y, wa.y, a10);
                a10 = fmaf(h1.z, wa.z, a10); a10 = fmaf(h1.w, wa.w, a10);
                a11 = fmaf(h1.x, wb.x, a11); a11 = fmaf(h1.y, wb.y, a11);
                a11 = fmaf(h1.z, wb.z, a11); a11 = fmaf(h1.w, wb.w, a11);
            }
            sh_g[((r0 + 0) * 8 + jj) * 4 + gp * 2 + 0] = a00;
            sh_g[((r0 + 0) * 8 + jj) * 4 + gp * 2 + 1] = a01;
            sh_g[((r0 + 1) * 8 + jj) * 4 + gp * 2 + 0] = a10;
            sh_g[((r0 + 1) * 8 + jj) * 4 + gp * 2 + 1] = a11;
        }
        __syncthreads();

        // cell update (rank space); frozen cells carry h in hreg, store skipped
        float* hnext = hb + (p ^ 1) * BB * HH;
        if (tt < wdl && tt < mylen) {
            float4 gv = *(float4*)&sh_g[tid * 4];
            float ig = fsig(gv.x);
            float fg = fsig(gv.y);
            float gg = ftanh(gv.z);
            float og = fsig(gv.w);
            float cn = fg * creg + ig * gg;
            creg = cn;
            hreg = og * ftanh(cn);
            __stcg(hnext + cr * HH + hcol, hreg);
        }
        __syncthreads();   // all alive hnext stores done CTA-wide

        if (s < TT - 1) {
            if (tid == 0) {
                asm volatile("red.release.gpu.global.add.u32 [%0], 1;"
                             :: "l"(&bar[s]) : "memory");
            }
            // prefetch next step's xg (hidden behind the barrier wait)
            const int tn2 = d ? (510 - s) : (s + 1);
            if (tn2 < wdl) {
                const float* xgn = g_xg + (((size_t)d * TT + tn2) * BB) * G4;
                x00 = __ldg(xgn + xo00); x01 = __ldg(xgn + xo01);
                x10 = __ldg(xgn + xo10); x11 = __ldg(xgn + xo11);
            }
            out[((size_t)(myb * TT + tt)) * 1024 + d * HH + hcol] = hreg;

            if (tid == 0) {
                unsigned v;
                for (;;) {
                    asm volatile("ld.acquire.gpu.global.u32 %0, [%1];"
                                 : "=r"(v) : "l"(&bar[s]) : "memory");
                    if (v >= 64u) break;
                    __nanosleep(32);
                }
            }
            __syncthreads();
        } else {
            out[((size_t)(myb * TT + tt)) * 1024 + d * HH + hcol] = hreg;
        }
    }
}

extern "C" void kernel_launch(void* const* d_in, const int* in_sizes, int n_in,
                              void* d_out, int out_size)
{
    const float* x    = (const float*)d_in[0];
    const int*   len  = (const int*)  d_in[1];
    const float* Wihf = (const float*)d_in[2];
    const float* Whhf = (const float*)d_in[3];
    const float* bihf = (const float*)d_in[4];
    const float* bhhf = (const float*)d_in[5];
    const float* Wihb = (const float*)d_in[6];
    const float* Whhb = (const float*)d_in[7];
    const float* bihb = (const float*)d_in[8];
    const float* bhhb = (const float*)d_in[9];
    float* out = (float*)d_out;

    void* barp = 0; void* hbp = 0;
    cudaGetSymbolAddress(&barp, g_bar);
    cudaGetSymbolAddress(&hbp,  g_hbuf);
    cudaMemsetAsync(barp, 0, 2 * TT * sizeof(unsigned));
    cudaMemsetAsync(hbp,  0, (size_t)2 * 2 * BB * HH * sizeof(float));

    dim3 ggrid(32, 128);
    gemm_xg_kernel<<<ggrid, 256>>>(x, Wihf, Wihb, bihf, bhhf, bihb, bhhb, len);

    cudaFuncSetAttribute(lstm_scan_kernel,
                         cudaFuncAttributeMaxDynamicSharedMemorySize, SCAN_SMEM_BYTES);
    lstm_scan_kernel<<<128, 256, SCAN_SMEM_BYTES>>>(len, Whhf, Whhb, out);
}